// round 1
// baseline (speedup 1.0000x reference)
#include <cuda_runtime.h>
#include <cuda_bf16.h>
#include <math.h>

#define NN 100000
#define EE 1600000
#define C0 128
#define C1 256
#define C3 128
#define NCLS 15
#define BN_EPS 1e-5

// ---------------- scratch (device globals; no allocation allowed) -------------
__device__ float  g_bufA  [(size_t)NN * 256];   // aggregated mean
__device__ float  g_bufPre[(size_t)NN * 256];   // pre-BN GEMM output
__device__ float  g_bufH1 [(size_t)NN * 256];   // activations (layer1, later layer3)
__device__ float  g_bufH2 [(size_t)NN * 256];   // activations (layer2)
__device__ int    g_cnt   [NN];
__device__ int    g_offs  [NN + 1];
__device__ int    g_cursor[NN];
__device__ int    g_bsum  [128];
__device__ int    g_src_sorted[EE];
__device__ double g_acc   [512];                // [0,256): sum, [256,512): sumsq
__device__ float  g_scale [256];
__device__ float  g_shift [256];
__device__ int    g_is64;

// ---------------- small utility kernels --------------------------------------
__global__ void k_zero_cnt() {
    int i = blockIdx.x * blockDim.x + threadIdx.x;
    if (i < NN) g_cnt[i] = 0;
}
__global__ void k_zero_acc() {
    int i = threadIdx.x;
    if (i < 512) g_acc[i] = 0.0;
}
// detect int64 vs int32 edge_index: values < 100000 -> int64 high words are all 0
__global__ void k_detect(const void* edges) {
    const int* p = (const int*)edges;
    int ok = 1;
    for (int i = 0; i < 64; i++)
        if (p[2 * i + 1] != 0) ok = 0;
    g_is64 = ok;
}

// ---------------- CSR construction --------------------------------------------
__global__ void k_hist(const void* edges) {
    int e = blockIdx.x * blockDim.x + threadIdx.x;
    if (e >= EE) return;
    int d;
    if (g_is64) d = (int)((const long long*)edges)[EE + e];
    else        d = ((const int*)edges)[EE + e];
    atomicAdd(&g_cnt[d], 1);
}

__global__ void k_scan1() {  // 98 blocks x 1024: per-block exclusive scan
    __shared__ int sh[1024];
    int i = blockIdx.x * 1024 + threadIdx.x;
    int v = (i < NN) ? g_cnt[i] : 0;
    sh[threadIdx.x] = v;
    __syncthreads();
    for (int off = 1; off < 1024; off <<= 1) {
        int t = (threadIdx.x >= off) ? sh[threadIdx.x - off] : 0;
        __syncthreads();
        sh[threadIdx.x] += t;
        __syncthreads();
    }
    if (i < NN) g_offs[i] = sh[threadIdx.x] - v;  // exclusive
    if (threadIdx.x == 1023) g_bsum[blockIdx.x] = sh[1023];
}

__global__ void k_scan2() {  // 1 block x 128: scan block sums (98 blocks)
    __shared__ int sh[128];
    int nb = (NN + 1023) / 1024;
    int v = (threadIdx.x < nb) ? g_bsum[threadIdx.x] : 0;
    sh[threadIdx.x] = v;
    __syncthreads();
    for (int off = 1; off < 128; off <<= 1) {
        int t = (threadIdx.x >= off) ? sh[threadIdx.x - off] : 0;
        __syncthreads();
        sh[threadIdx.x] += t;
        __syncthreads();
    }
    g_bsum[threadIdx.x] = sh[threadIdx.x] - v;    // exclusive
}

__global__ void k_scan3() {
    int i = blockIdx.x * blockDim.x + threadIdx.x;
    if (i < NN) {
        int off = g_offs[i] + g_bsum[i >> 10];
        g_offs[i]   = off;
        g_cursor[i] = off;
    }
    if (i == 0) g_offs[NN] = EE;
}

__global__ void k_fill(const void* edges) {
    int e = blockIdx.x * blockDim.x + threadIdx.x;
    if (e >= EE) return;
    int s, d;
    if (g_is64) {
        const long long* p = (const long long*)edges;
        s = (int)p[e]; d = (int)p[EE + e];
    } else {
        const int* p = (const int*)edges;
        s = p[e]; d = p[EE + e];
    }
    int pos = atomicAdd(&g_cursor[d], 1);
    g_src_sorted[pos] = s;
}

// ---------------- mean aggregation (gather over CSR) ---------------------------
template <int D>
__global__ void k_agg(const float* __restrict__ x, float* __restrict__ outMean) {
    constexpr int G  = D / 4;     // lanes per node (32 or 64), float4 each
    constexpr int NG = 128 / G;   // node groups per block
    int group = threadIdx.x / G;
    int lane  = threadIdx.x % G;
    int node  = blockIdx.x * NG + group;
    if (node >= NN) return;
    int beg = g_offs[node], end = g_offs[node + 1];
    float4 acc = make_float4(0.f, 0.f, 0.f, 0.f);
    const float4* xv = (const float4*)x;
    for (int e = beg; e < end; e++) {
        int s = g_src_sorted[e];
        float4 v = xv[(size_t)s * G + lane];
        acc.x += v.x; acc.y += v.y; acc.z += v.z; acc.w += v.w;
    }
    float inv = 1.0f / fmaxf((float)(end - beg), 1.0f);
    float4 o = make_float4(acc.x * inv, acc.y * inv, acc.z * inv, acc.w * inv);
    ((float4*)outMean)[(size_t)node * G + lane] = o;
}

// ---------------- fused dual GEMM: C = A1@B1^T + A2@B2^T + bias ----------------
// A1,A2: [NN, DI] row-major; B1,B2: [DO, DI] row-major; C: [NN, DO]
template <int DI, int DO>
__global__ __launch_bounds__(256) void k_gemm_dual(
    const float* __restrict__ A1, const float* __restrict__ A2,
    const float* __restrict__ B1, const float* __restrict__ B2,
    const float* __restrict__ bias, float* __restrict__ C)
{
    constexpr int BM = 64, BN = 64, BK = 16;
    __shared__ float As[BK][BM + 4];
    __shared__ float Bs[BK][BN + 4];
    const int tid = threadIdx.x;
    const int tx = tid & 15;    // 0..15 -> 4 output cols
    const int ty = tid >> 4;    // 0..15 -> 4 output rows
    const int rowBase = blockIdx.x * BM;
    const int colBase = blockIdx.y * BN;
    const int lRow = tid >> 2;        // 0..63
    const int lK   = (tid & 3) * 4;   // 0,4,8,12
    const int gr = rowBase + lRow;
    const int gc = colBase + lRow;    // always < DO (DO % 64 == 0)
    float acc[4][4] = {};

    for (int kt = 0; kt < 2 * DI; kt += BK) {
        const float* Ap = (kt < DI) ? A1 : A2;
        const float* Bp = (kt < DI) ? B1 : B2;
        const int kk = (kt < DI) ? kt : (kt - DI);
        float4 av = make_float4(0.f, 0.f, 0.f, 0.f);
        if (gr < NN)
            av = *reinterpret_cast<const float4*>(Ap + (size_t)gr * DI + kk + lK);
        float4 bv = *reinterpret_cast<const float4*>(Bp + (size_t)gc * DI + kk + lK);
        As[lK + 0][lRow] = av.x; As[lK + 1][lRow] = av.y;
        As[lK + 2][lRow] = av.z; As[lK + 3][lRow] = av.w;
        Bs[lK + 0][lRow] = bv.x; Bs[lK + 1][lRow] = bv.y;
        Bs[lK + 2][lRow] = bv.z; Bs[lK + 3][lRow] = bv.w;
        __syncthreads();
#pragma unroll
        for (int k = 0; k < BK; k++) {
            float4 a = *reinterpret_cast<const float4*>(&As[k][ty * 4]);
            float4 b = *reinterpret_cast<const float4*>(&Bs[k][tx * 4]);
            acc[0][0] += a.x * b.x; acc[0][1] += a.x * b.y; acc[0][2] += a.x * b.z; acc[0][3] += a.x * b.w;
            acc[1][0] += a.y * b.x; acc[1][1] += a.y * b.y; acc[1][2] += a.y * b.z; acc[1][3] += a.y * b.w;
            acc[2][0] += a.z * b.x; acc[2][1] += a.z * b.y; acc[2][2] += a.z * b.z; acc[2][3] += a.z * b.w;
            acc[3][0] += a.w * b.x; acc[3][1] += a.w * b.y; acc[3][2] += a.w * b.z; acc[3][3] += a.w * b.w;
        }
        __syncthreads();
    }
    float4 bb = *reinterpret_cast<const float4*>(bias + colBase + tx * 4);
#pragma unroll
    for (int i = 0; i < 4; i++) {
        int r = rowBase + ty * 4 + i;
        if (r < NN) {
            float4 o;
            o.x = acc[i][0] + bb.x; o.y = acc[i][1] + bb.y;
            o.z = acc[i][2] + bb.z; o.w = acc[i][3] + bb.w;
            *reinterpret_cast<float4*>(C + (size_t)r * DO + colBase + tx * 4) = o;
        }
    }
}

// ---------------- BN statistics (double accumulation) --------------------------
template <int D>
__global__ void k_stats(const float* __restrict__ pre) {
    constexpr int RPI = 256 / D;       // rows per iteration per block (1 or 2)
    int col = threadIdx.x % D;
    int rl  = threadIdx.x / D;
    double s = 0.0, sq = 0.0;
    for (int r = blockIdx.x * RPI + rl; r < NN; r += gridDim.x * RPI) {
        float v = pre[(size_t)r * D + col];
        s  += (double)v;
        sq += (double)v * (double)v;
    }
    if (RPI == 2) {
        __shared__ double sh1[256], sh2[256];
        sh1[threadIdx.x] = s; sh2[threadIdx.x] = sq;
        __syncthreads();
        if (rl == 0) { s += sh1[threadIdx.x + D]; sq += sh2[threadIdx.x + D]; }
    }
    if (rl == 0) {
        atomicAdd(&g_acc[col], s);
        atomicAdd(&g_acc[256 + col], sq);
    }
}

template <int D>
__global__ void k_finalize(const float* __restrict__ g, const float* __restrict__ b) {
    int c = threadIdx.x;
    if (c < D) {
        double mu  = g_acc[c] / (double)NN;
        double var = g_acc[256 + c] / (double)NN - mu * mu;
        double rs  = 1.0 / sqrt(var + BN_EPS);
        double sc  = (double)g[c] * rs;
        g_scale[c] = (float)sc;
        g_shift[c] = (float)((double)b[c] - mu * sc);
    }
}

template <int D>
__global__ void k_bn_relu(const float* __restrict__ in, float* __restrict__ out) {
    int i = blockIdx.x * blockDim.x + threadIdx.x;
    int total4 = NN * D / 4;
    if (i >= total4) return;
    int c4 = (i & (D / 4 - 1)) * 4;
    float4 v  = ((const float4*)in)[i];
    float4 sc = *(const float4*)&g_scale[c4];
    float4 sh = *(const float4*)&g_shift[c4];
    float4 o;
    o.x = fmaxf(v.x * sc.x + sh.x, 0.f);
    o.y = fmaxf(v.y * sc.y + sh.y, 0.f);
    o.z = fmaxf(v.z * sc.z + sh.z, 0.f);
    o.w = fmaxf(v.w * sc.w + sh.w, 0.f);
    ((float4*)out)[i] = o;
}

// ---------------- classifier: out[N,15] = h[N,128] @ wc^T + bc -----------------
__global__ __launch_bounds__(256) void k_classifier(
    const float* __restrict__ h, const float* __restrict__ wc,
    const float* __restrict__ bc, float* __restrict__ out)
{
    __shared__ float4 wsh[NCLS * 32];
    __shared__ float  bsh[NCLS];
    int tid = threadIdx.x;
    for (int i = tid; i < NCLS * 32; i += 256) wsh[i] = ((const float4*)wc)[i];
    if (tid < NCLS) bsh[tid] = bc[tid];
    __syncthreads();
    int warp = tid >> 5, lane = tid & 31;
    int row = blockIdx.x * 8 + warp;
    if (row >= NN) return;
    float4 hv = ((const float4*)h)[(size_t)row * 32 + lane];
#pragma unroll
    for (int j = 0; j < NCLS; j++) {
        float4 w = wsh[j * 32 + lane];
        float p = hv.x * w.x + hv.y * w.y + hv.z * w.z + hv.w * w.w;
#pragma unroll
        for (int o = 16; o > 0; o >>= 1) p += __shfl_xor_sync(0xFFFFFFFFu, p, o);
        if (lane == 0) out[(size_t)row * NCLS + j] = p + bsh[j];
    }
}

// ---------------- driver --------------------------------------------------------
extern "C" void kernel_launch(void* const* d_in, const int* in_sizes, int n_in,
                              void* d_out, int out_size)
{
    const float* x     = (const float*)d_in[0];
    const void*  edges = d_in[1];
    const float* w1_l = (const float*)d_in[2];
    const float* b1_l = (const float*)d_in[3];
    const float* w1_r = (const float*)d_in[4];
    const float* g1   = (const float*)d_in[5];
    const float* be1  = (const float*)d_in[6];
    const float* w2_l = (const float*)d_in[7];
    const float* b2_l = (const float*)d_in[8];
    const float* w2_r = (const float*)d_in[9];
    const float* g2   = (const float*)d_in[10];
    const float* be2  = (const float*)d_in[11];
    const float* w3_l = (const float*)d_in[12];
    const float* b3_l = (const float*)d_in[13];
    const float* w3_r = (const float*)d_in[14];
    const float* g3   = (const float*)d_in[15];
    const float* be3  = (const float*)d_in[16];
    const float* wc   = (const float*)d_in[17];
    const float* bc   = (const float*)d_in[18];
    float* out = (float*)d_out;

    // resolve device-global buffer pointers lazily (kernels reference globals,
    // but GEMM/agg/etc take pointers so they can be reused across layers)
    static float *bufA = nullptr, *bufPre = nullptr, *bufH1 = nullptr, *bufH2 = nullptr;
    if (!bufA) {
        cudaGetSymbolAddress((void**)&bufA,   g_bufA);
        cudaGetSymbolAddress((void**)&bufPre, g_bufPre);
        cudaGetSymbolAddress((void**)&bufH1,  g_bufH1);
        cudaGetSymbolAddress((void**)&bufH2,  g_bufH2);
    }

    const int EB = (EE + 255) / 256;
    const int NB = (NN + 255) / 256;

    // ---- CSR build (once per call; reused by all 3 layers) ----
    k_detect<<<1, 1>>>(edges);
    k_zero_cnt<<<NB, 256>>>();
    k_hist<<<EB, 256>>>(edges);
    k_scan1<<<(NN + 1023) / 1024, 1024>>>();
    k_scan2<<<1, 128>>>();
    k_scan3<<<NB, 256>>>();
    k_fill<<<EB, 256>>>(edges);

    const int gemmM = (NN + 63) / 64;

    // ---- layer 1: 128 -> 256 ----
    k_agg<C0><<<(NN + 3) / 4, 128>>>(x, bufA);
    k_gemm_dual<C0, C1><<<dim3(gemmM, C1 / 64), 256>>>(bufA, x, w1_l, w1_r, b1_l, bufPre);
    k_zero_acc<<<1, 512>>>();
    k_stats<C1><<<1024, 256>>>(bufPre);
    k_finalize<C1><<<1, 256>>>(g1, be1);
    k_bn_relu<C1><<<(NN * C1 / 4 + 255) / 256, 256>>>(bufPre, bufH1);

    // ---- layer 2: 256 -> 256 ----
    k_agg<C1><<<(NN + 1) / 2, 128>>>(bufH1, bufA);
    k_gemm_dual<C1, C1><<<dim3(gemmM, C1 / 64), 256>>>(bufA, bufH1, w2_l, w2_r, b2_l, bufPre);
    k_zero_acc<<<1, 512>>>();
    k_stats<C1><<<1024, 256>>>(bufPre);
    k_finalize<C1><<<1, 256>>>(g2, be2);
    k_bn_relu<C1><<<(NN * C1 / 4 + 255) / 256, 256>>>(bufPre, bufH2);

    // ---- layer 3: 256 -> 128 ----
    k_agg<C1><<<(NN + 1) / 2, 128>>>(bufH2, bufA);
    k_gemm_dual<C1, C3><<<dim3(gemmM, C3 / 64), 256>>>(bufA, bufH2, w3_l, w3_r, b3_l, bufPre);
    k_zero_acc<<<1, 512>>>();
    k_stats<C3><<<1024, 256>>>(bufPre);
    k_finalize<C3><<<1, 128>>>(g3, be3);
    k_bn_relu<C3><<<(NN * C3 / 4 + 255) / 256, 256>>>(bufPre, bufH1);

    // ---- classifier: 128 -> 15 ----
    k_classifier<<<(NN + 7) / 8, 256>>>(bufH1, wc, bc, out);
}

// round 3
// speedup vs baseline: 1.4992x; 1.4992x over previous
#include <cuda_runtime.h>
#include <cuda_bf16.h>
#include <math.h>
#include <stdint.h>

#define NN 100000
#define NN_PAD 100096          // 782 * 128
#define EE 1600000
#define C0 128
#define C1 256
#define C3 128
#define NCLS 15
#define BN_EPS 1e-5

// ---------------- scratch (device globals; no allocation allowed) -------------
__device__ float  g_pre  [(size_t)NN_PAD * 256];   // pre-BN GEMM output (fp32)
__device__ float  g_actF [(size_t)NN_PAD * 256];   // current activations (fp32, agg input)
__device__ __nv_bfloat16 g_meanH[(size_t)NN_PAD * 256];
__device__ __nv_bfloat16 g_meanL[(size_t)NN_PAD * 256];
__device__ __nv_bfloat16 g_actH [(size_t)NN_PAD * 256];
__device__ __nv_bfloat16 g_actL [(size_t)NN_PAD * 256];
__device__ __nv_bfloat16 g_xH   [(size_t)NN_PAD * 128];
__device__ __nv_bfloat16 g_xL   [(size_t)NN_PAD * 128];
__device__ __nv_bfloat16 g_w[12][65536];           // weight hi/lo splits
__device__ int    g_cnt   [NN];
__device__ int    g_offs  [NN + 1];
__device__ int    g_cursor[NN];
__device__ int    g_bsum  [128];
__device__ int    g_src_sorted[EE];
__device__ double g_acc   [512];
__device__ float  g_scale [256];
__device__ float  g_shift [256];
__device__ int    g_is64;

// ---------------- PTX helpers ---------------------------------------------------
__device__ __forceinline__ uint32_t smem_u32(const void* p) {
    uint32_t a;
    asm("{ .reg .u64 t; cvta.to.shared.u64 t, %1; cvt.u32.u64 %0, t; }" : "=r"(a) : "l"(p));
    return a;
}
#define CP_ASYNC16(sa, g) \
    asm volatile("cp.async.cg.shared.global [%0], [%1], 16;" :: "r"(sa), "l"(g) : "memory")
#define CP_COMMIT() asm volatile("cp.async.commit_group;" ::: "memory")
#define LDSM4(r, a) \
    asm volatile("ldmatrix.sync.aligned.m8n8.x4.shared.b16 {%0,%1,%2,%3}, [%4];" \
        : "=r"((r)[0]), "=r"((r)[1]), "=r"((r)[2]), "=r"((r)[3]) : "r"(a))
#define MMA16816(d, a, b) \
    asm volatile("mma.sync.aligned.m16n8k16.row.col.f32.bf16.bf16.f32 " \
        "{%0,%1,%2,%3}, {%4,%5,%6,%7}, {%8,%9}, {%0,%1,%2,%3};" \
        : "+f"((d)[0]), "+f"((d)[1]), "+f"((d)[2]), "+f"((d)[3]) \
        : "r"((a)[0]), "r"((a)[1]), "r"((a)[2]), "r"((a)[3]), "r"((b)[0]), "r"((b)[1]))

// ---------------- small utility kernels --------------------------------------
__global__ void k_zero_cnt() {
    int i = blockIdx.x * blockDim.x + threadIdx.x;
    if (i < NN) g_cnt[i] = 0;
}
__global__ void k_zero_acc() {
    int i = threadIdx.x;
    if (i < 512) g_acc[i] = 0.0;
}
__global__ void k_detect(const void* edges) {
    const int* p = (const int*)edges;
    int ok = 1;
    for (int i = 0; i < 64; i++)
        if (p[2 * i + 1] != 0) ok = 0;
    g_is64 = ok;
}
// fp32 -> bf16 hi/lo split (x and weights)
__global__ void k_split(const float* __restrict__ in, __nv_bfloat16* __restrict__ h,
                        __nv_bfloat16* __restrict__ l, int n) {
    int i = blockIdx.x * blockDim.x + threadIdx.x;
    if (i < n) {
        float v = in[i];
        __nv_bfloat16 hh = __float2bfloat16_rn(v);
        h[i] = hh;
        l[i] = __float2bfloat16_rn(v - __bfloat162float(hh));
    }
}

// ---------------- CSR construction --------------------------------------------
__global__ void k_hist(const void* edges) {
    int e = blockIdx.x * blockDim.x + threadIdx.x;
    if (e >= EE) return;
    int d;
    if (g_is64) d = (int)((const long long*)edges)[EE + e];
    else        d = ((const int*)edges)[EE + e];
    atomicAdd(&g_cnt[d], 1);
}
__global__ void k_scan1() {
    __shared__ int sh[1024];
    int i = blockIdx.x * 1024 + threadIdx.x;
    int v = (i < NN) ? g_cnt[i] : 0;
    sh[threadIdx.x] = v;
    __syncthreads();
    for (int off = 1; off < 1024; off <<= 1) {
        int t = (threadIdx.x >= off) ? sh[threadIdx.x - off] : 0;
        __syncthreads();
        sh[threadIdx.x] += t;
        __syncthreads();
    }
    if (i < NN) g_offs[i] = sh[threadIdx.x] - v;
    if (threadIdx.x == 1023) g_bsum[blockIdx.x] = sh[1023];
}
__global__ void k_scan2() {
    __shared__ int sh[128];
    int nb = (NN + 1023) / 1024;
    int v = (threadIdx.x < nb) ? g_bsum[threadIdx.x] : 0;
    sh[threadIdx.x] = v;
    __syncthreads();
    for (int off = 1; off < 128; off <<= 1) {
        int t = (threadIdx.x >= off) ? sh[threadIdx.x - off] : 0;
        __syncthreads();
        sh[threadIdx.x] += t;
        __syncthreads();
    }
    g_bsum[threadIdx.x] = sh[threadIdx.x] - v;
}
__global__ void k_scan3() {
    int i = blockIdx.x * blockDim.x + threadIdx.x;
    if (i < NN) {
        int off = g_offs[i] + g_bsum[i >> 10];
        g_offs[i]   = off;
        g_cursor[i] = off;
    }
    if (i == 0) g_offs[NN] = EE;
}
__global__ void k_fill(const void* edges) {
    int e = blockIdx.x * blockDim.x + threadIdx.x;
    if (e >= EE) return;
    int s, d;
    if (g_is64) {
        const long long* p = (const long long*)edges;
        s = (int)p[e]; d = (int)p[EE + e];
    } else {
        const int* p = (const int*)edges;
        s = p[e]; d = p[EE + e];
    }
    int pos = atomicAdd(&g_cursor[d], 1);
    g_src_sorted[pos] = s;
}

// ---------------- mean aggregation: gather + fused bf16 hi/lo split -------------
template <int D>
__global__ void k_agg(const float* __restrict__ x, __nv_bfloat16* __restrict__ mh,
                      __nv_bfloat16* __restrict__ ml) {
    constexpr int G  = D / 4;
    constexpr int NG = 128 / G;
    int group = threadIdx.x / G;
    int lane  = threadIdx.x % G;
    int node  = blockIdx.x * NG + group;
    if (node >= NN) return;
    int beg = g_offs[node], end = g_offs[node + 1];
    float4 acc = make_float4(0.f, 0.f, 0.f, 0.f);
    const float4* xv = (const float4*)x;
    for (int e = beg; e < end; e++) {
        int s = g_src_sorted[e];
        float4 v = xv[(size_t)s * G + lane];
        acc.x += v.x; acc.y += v.y; acc.z += v.z; acc.w += v.w;
    }
    float inv = 1.0f / fmaxf((float)(end - beg), 1.0f);
    float o[4] = {acc.x * inv, acc.y * inv, acc.z * inv, acc.w * inv};
    __nv_bfloat16 hv[4], lv[4];
#pragma unroll
    for (int q = 0; q < 4; q++) {
        hv[q] = __float2bfloat16_rn(o[q]);
        lv[q] = __float2bfloat16_rn(o[q] - __bfloat162float(hv[q]));
    }
    size_t base = (size_t)node * D + lane * 4;
    *(uint2*)(mh + base) = *(uint2*)hv;
    *(uint2*)(ml + base) = *(uint2*)lv;
}

// ---------------- mma.sync dual GEMM + hi/lo compensation -----------------------
// C[M,DO] = (A1h+A1l)@(B1h+B1l)^T + (A2h+A2l)@(B2h+B2l)^T  (lo*lo dropped)
// 6 K-segments of DI each, as K-concat; block tile 128x128, BK=32, 8 warps.
template <int DI, int DO>
__global__ __launch_bounds__(256) void k_gemm_mma(
    const __nv_bfloat16* __restrict__ A1h, const __nv_bfloat16* __restrict__ A1l,
    const __nv_bfloat16* __restrict__ A2h, const __nv_bfloat16* __restrict__ A2l,
    const __nv_bfloat16* __restrict__ B1h, const __nv_bfloat16* __restrict__ B1l,
    const __nv_bfloat16* __restrict__ B2h, const __nv_bfloat16* __restrict__ B2l,
    float* __restrict__ C)
{
    constexpr int CH_PER_SEG = DI / 32;
    constexpr int NCH = 6 * CH_PER_SEG;
    // [stage][A(128x32)+B(128x32)], rows padded to 80B -> conflict-free ldmatrix
    __shared__ __align__(128) char smem[2 * 2 * 128 * 80];
    const uint32_t sbase = smem_u32(smem);
    const int tid = threadIdx.x;
    const int wid = tid >> 5, lane = tid & 31;
    const int wr = wid >> 2, wcn = wid & 3;        // warp row (0..1), warp col (0..3)
    const int rowBase = blockIdx.x * 128;
    const int colBase = blockIdx.y * 128;

    const __nv_bfloat16* Asrc[6] = {A1h, A1h, A1l, A2h, A2h, A2l};
    const __nv_bfloat16* Bsrc[6] = {B1h, B1l, B1h, B2h, B2l, B2h};

    // per-thread load slots: 2 A + 2 B x 16B
    const int lrow = tid >> 2;          // 0..63
    const int lcg  = tid & 3;           // 16B group within 64B row
    const uint32_t sA0 = sbase + lrow * 80 + lcg * 16;
    const uint32_t sB0 = sbase + 10240 + lrow * 80 + lcg * 16;

    auto load = [&](int c) {
        const int s = c & 1;
        const int seg = c / CH_PER_SEG;
        const int kk = (c % CH_PER_SEG) * 32;
        const __nv_bfloat16* Ap = Asrc[seg] + (size_t)rowBase * DI + kk + lcg * 8;
        const __nv_bfloat16* Bp = Bsrc[seg] + (size_t)colBase * DI + kk + lcg * 8;
        const uint32_t so = s * 20480u;
        CP_ASYNC16(sA0 + so,        Ap + (size_t)lrow * DI);
        CP_ASYNC16(sA0 + so + 5120, Ap + (size_t)(lrow + 64) * DI);
        CP_ASYNC16(sB0 + so,        Bp + (size_t)lrow * DI);
        CP_ASYNC16(sB0 + so + 5120, Bp + (size_t)(lrow + 64) * DI);
        CP_COMMIT();
    };

    float acc[4][4][4] = {};
    // precomputed ldmatrix lane addresses (stage-0 base; add stage offset later)
    const uint32_t aAddr = sbase + (wr * 64 + (lane & 15)) * 80 + (lane >> 4) * 16;
    const uint32_t bAddr = sbase + 10240 +
        (wcn * 32 + (lane & 7) + ((lane >> 4) << 3)) * 80 + ((lane >> 3) & 1) * 16;

    load(0);
    for (int c = 0; c < NCH; c++) {
        const int s = c & 1;
        if (c + 1 < NCH) {
            load(c + 1);
            asm volatile("cp.async.wait_group 1;" ::: "memory");
        } else {
            asm volatile("cp.async.wait_group 0;" ::: "memory");
        }
        __syncthreads();
        const uint32_t so = s * 20480u;
#pragma unroll
        for (int kb = 0; kb < 2; kb++) {           // two k16 halves of BK=32
            uint32_t afr[4][4], bfr[4][2];
#pragma unroll
            for (int mt = 0; mt < 4; mt++)
                LDSM4(afr[mt], aAddr + so + mt * (16 * 80) + kb * 32);
#pragma unroll
            for (int ntp = 0; ntp < 2; ntp++) {
                uint32_t r[4];
                LDSM4(r, bAddr + so + ntp * (16 * 80) + kb * 32);
                bfr[ntp * 2][0] = r[0]; bfr[ntp * 2][1] = r[1];
                bfr[ntp * 2 + 1][0] = r[2]; bfr[ntp * 2 + 1][1] = r[3];
            }
#pragma unroll
            for (int mt = 0; mt < 4; mt++)
#pragma unroll
                for (int nt = 0; nt < 4; nt++)
                    MMA16816(acc[mt][nt], afr[mt], bfr[nt]);
        }
        __syncthreads();
    }

    // epilogue: write fp32 C
#pragma unroll
    for (int mt = 0; mt < 4; mt++) {
        const int r0 = rowBase + wr * 64 + mt * 16 + (lane >> 2);
#pragma unroll
        for (int nt = 0; nt < 4; nt++) {
            const int cc = colBase + wcn * 32 + nt * 8 + (lane & 3) * 2;
            if (r0 < NN)
                *(float2*)(C + (size_t)r0 * DO + cc) =
                    make_float2(acc[mt][nt][0], acc[mt][nt][1]);
            if (r0 + 8 < NN)
                *(float2*)(C + (size_t)(r0 + 8) * DO + cc) =
                    make_float2(acc[mt][nt][2], acc[mt][nt][3]);
        }
    }
}

// ---------------- BN statistics (double accumulation) --------------------------
template <int D>
__global__ void k_stats(const float* __restrict__ pre) {
    constexpr int RPI = 256 / D;
    int col = threadIdx.x % D;
    int rl  = threadIdx.x / D;
    double s = 0.0, sq = 0.0;
    for (int r = blockIdx.x * RPI + rl; r < NN; r += gridDim.x * RPI) {
        float v = pre[(size_t)r * D + col];
        s  += (double)v;
        sq += (double)v * (double)v;
    }
    if (RPI == 2) {
        __shared__ double sh1[256], sh2[256];
        sh1[threadIdx.x] = s; sh2[threadIdx.x] = sq;
        __syncthreads();
        if (rl == 0) { s += sh1[threadIdx.x + D]; sq += sh2[threadIdx.x + D]; }
    }
    if (rl == 0) {
        atomicAdd(&g_acc[col], s);
        atomicAdd(&g_acc[256 + col], sq);
    }
}
template <int D>
__global__ void k_finalize(const float* __restrict__ g, const float* __restrict__ b) {
    int c = threadIdx.x;
    if (c < D) {
        double mu  = g_acc[c] / (double)NN;
        double var = g_acc[256 + c] / (double)NN - mu * mu;
        double rs  = 1.0 / sqrt(var + BN_EPS);
        double sc  = (double)g[c] * rs;
        g_scale[c] = (float)sc;
        g_shift[c] = (float)((double)b[c] - mu * sc);
    }
}
// BN + ReLU + fused bf16 hi/lo split of activations
template <int D, bool SPLIT>
__global__ void k_bn_relu(const float* __restrict__ in, float* __restrict__ outF,
                          __nv_bfloat16* __restrict__ outH, __nv_bfloat16* __restrict__ outL) {
    int i = blockIdx.x * blockDim.x + threadIdx.x;
    int total4 = NN * D / 4;
    if (i >= total4) return;
    int c4 = (i & (D / 4 - 1)) * 4;
    float4 v  = ((const float4*)in)[i];
    float4 sc = *(const float4*)&g_scale[c4];
    float4 sh = *(const float4*)&g_shift[c4];
    float o[4];
    o[0] = fmaxf(v.x * sc.x + sh.x, 0.f);
    o[1] = fmaxf(v.y * sc.y + sh.y, 0.f);
    o[2] = fmaxf(v.z * sc.z + sh.z, 0.f);
    o[3] = fmaxf(v.w * sc.w + sh.w, 0.f);
    ((float4*)outF)[i] = make_float4(o[0], o[1], o[2], o[3]);
    if (SPLIT) {
        __nv_bfloat16 hv[4], lv[4];
#pragma unroll
        for (int q = 0; q < 4; q++) {
            hv[q] = __float2bfloat16_rn(o[q]);
            lv[q] = __float2bfloat16_rn(o[q] - __bfloat162float(hv[q]));
        }
        *(uint2*)(outH + (size_t)i * 4) = *(uint2*)hv;
        *(uint2*)(outL + (size_t)i * 4) = *(uint2*)lv;
    }
}

// ---------------- classifier: out[N,15] = h[N,128] @ wc^T + bc -----------------
__global__ __launch_bounds__(256) void k_classifier(
    const float* __restrict__ h, const float* __restrict__ wc,
    const float* __restrict__ bc, float* __restrict__ out)
{
    __shared__ float4 wsh[NCLS * 32];
    __shared__ float  bsh[NCLS];
    int tid = threadIdx.x;
    for (int i = tid; i < NCLS * 32; i += 256) wsh[i] = ((const float4*)wc)[i];
    if (tid < NCLS) bsh[tid] = bc[tid];
    __syncthreads();
    int warp = tid >> 5, lane = tid & 31;
    int row = blockIdx.x * 8 + warp;
    if (row >= NN) return;
    float4 hv = ((const float4*)h)[(size_t)row * 32 + lane];
#pragma unroll
    for (int j = 0; j < NCLS; j++) {
        float4 w = wsh[j * 32 + lane];
        float p = hv.x * w.x + hv.y * w.y + hv.z * w.z + hv.w * w.w;
#pragma unroll
        for (int o = 16; o > 0; o >>= 1) p += __shfl_xor_sync(0xFFFFFFFFu, p, o);
        if (lane == 0) out[(size_t)row * NCLS + j] = p + bsh[j];
    }
}

// ---------------- driver --------------------------------------------------------
extern "C" void kernel_launch(void* const* d_in, const int* in_sizes, int n_in,
                              void* d_out, int out_size)
{
    const float* x     = (const float*)d_in[0];
    const void*  edges = d_in[1];
    const float* w1_l = (const float*)d_in[2];
    const float* w1_r = (const float*)d_in[4];
    const float* g1   = (const float*)d_in[5];
    const float* be1  = (const float*)d_in[6];
    const float* w2_l = (const float*)d_in[7];
    const float* w2_r = (const float*)d_in[9];
    const float* g2   = (const float*)d_in[10];
    const float* be2  = (const float*)d_in[11];
    const float* w3_l = (const float*)d_in[12];
    const float* w3_r = (const float*)d_in[14];
    const float* g3   = (const float*)d_in[15];
    const float* be3  = (const float*)d_in[16];
    const float* wc   = (const float*)d_in[17];
    const float* bc   = (const float*)d_in[18];
    float* out = (float*)d_out;

    static float *pre = nullptr, *actF = nullptr;
    static __nv_bfloat16 *meanH, *meanL, *actH, *actL, *xH, *xL, *wbuf;
    if (!pre) {
        cudaGetSymbolAddress((void**)&pre,   g_pre);
        cudaGetSymbolAddress((void**)&actF,  g_actF);
        cudaGetSymbolAddress((void**)&meanH, g_meanH);
        cudaGetSymbolAddress((void**)&meanL, g_meanL);
        cudaGetSymbolAddress((void**)&actH,  g_actH);
        cudaGetSymbolAddress((void**)&actL,  g_actL);
        cudaGetSymbolAddress((void**)&xH,    g_xH);
        cudaGetSymbolAddress((void**)&xL,    g_xL);
        cudaGetSymbolAddress((void**)&wbuf,  g_w);
    }
    auto W = [&](int i) { return wbuf + (size_t)i * 65536; };

    const int EB = (EE + 255) / 256;
    const int NB = (NN + 255) / 256;

    // ---- CSR build ----
    k_detect<<<1, 1>>>(edges);
    k_zero_cnt<<<NB, 256>>>();
    k_hist<<<EB, 256>>>(edges);
    k_scan1<<<(NN + 1023) / 1024, 1024>>>();
    k_scan2<<<1, 128>>>();
    k_scan3<<<NB, 256>>>();
    k_fill<<<EB, 256>>>(edges);

    // ---- splits: weights + x ----
    k_split<<<(32768 + 255) / 256, 256>>>(w1_l, W(0), W(1), 256 * 128);
    k_split<<<(32768 + 255) / 256, 256>>>(w1_r, W(2), W(3), 256 * 128);
    k_split<<<(65536 + 255) / 256, 256>>>(w2_l, W(4), W(5), 256 * 256);
    k_split<<<(65536 + 255) / 256, 256>>>(w2_r, W(6), W(7), 256 * 256);
    k_split<<<(32768 + 255) / 256, 256>>>(w3_l, W(8), W(9), 128 * 256);
    k_split<<<(32768 + 255) / 256, 256>>>(w3_r, W(10), W(11), 128 * 256);
    k_split<<<(NN * 128 + 255) / 256, 256>>>(x, xH, xL, NN * 128);

    const int MT = NN_PAD / 128;  // 782 M-tiles

    // ---- layer 1: 128 -> 256 ----
    k_agg<C0><<<(NN + 3) / 4, 128>>>(x, meanH, meanL);
    k_gemm_mma<128, 256><<<dim3(MT, 2), 256>>>(meanH, meanL, xH, xL,
                                               W(0), W(1), W(2), W(3), pre);
    k_zero_acc<<<1, 512>>>();
    k_stats<C1><<<1024, 256>>>(pre);
    k_finalize<C1><<<1, 256>>>(g1, be1);
    k_bn_relu<C1, true><<<(NN * C1 / 4 + 255) / 256, 256>>>(pre, actF, actH, actL);

    // ---- layer 2: 256 -> 256 ----
    k_agg<C1><<<(NN + 1) / 2, 128>>>(actF, meanH, meanL);
    k_gemm_mma<256, 256><<<dim3(MT, 2), 256>>>(meanH, meanL, actH, actL,
                                               W(4), W(5), W(6), W(7), pre);
    k_zero_acc<<<1, 512>>>();
    k_stats<C1><<<1024, 256>>>(pre);
    k_finalize<C1><<<1, 256>>>(g2, be2);
    k_bn_relu<C1, true><<<(NN * C1 / 4 + 255) / 256, 256>>>(pre, actF, actH, actL);

    // ---- layer 3: 256 -> 128 ----
    k_agg<C1><<<(NN + 1) / 2, 128>>>(actF, meanH, meanL);
    k_gemm_mma<256, 128><<<dim3(MT, 1), 256>>>(meanH, meanL, actH, actL,
                                               W(8), W(9), W(10), W(11), pre);
    k_zero_acc<<<1, 512>>>();
    k_stats<C3><<<1024, 256>>>(pre);
    k_finalize<C3><<<1, 128>>>(g3, be3);
    k_bn_relu<C3, false><<<(NN * C3 / 4 + 255) / 256, 256>>>(pre, actF, nullptr, nullptr);

    // ---- classifier ----
    k_classifier<<<(NN + 7) / 8, 256>>>(actF, wc, bc, out);
}

// round 4
// speedup vs baseline: 1.8853x; 1.2575x over previous
#include <cuda_runtime.h>
#include <cuda_bf16.h>
#include <math.h>
#include <stdint.h>

#define NN 100000
#define NN_PAD 100096          // 782 * 128
#define EE 1600000
#define C0 128
#define C1 256
#define C3 128
#define NCLS 15
#define BN_EPS 1e-5

// ---------------- scratch (device globals; zero-initialized, no allocation) ----
__device__ float  g_pre  [(size_t)NN_PAD * 256];   // GEMM output (fp32)
__device__ float  g_pre3 [(size_t)NN_PAD * 128];   // layer-3 post-agg result
__device__ __nv_bfloat16 g_meanH[(size_t)NN_PAD * 256];
__device__ __nv_bfloat16 g_meanL[(size_t)NN_PAD * 256];
__device__ __nv_bfloat16 g_actH [(size_t)NN_PAD * 256];
__device__ __nv_bfloat16 g_actL [(size_t)NN_PAD * 256];
__device__ __nv_bfloat16 g_xH   [(size_t)NN_PAD * 128];
__device__ __nv_bfloat16 g_xL   [(size_t)NN_PAD * 128];
__device__ __nv_bfloat16 g_w[12][65536];           // weight hi/lo splits
__device__ int    g_cnt   [NN];
__device__ int    g_offs  [NN + 1];
__device__ int    g_cursor[NN];
__device__ int    g_bsum  [128];
__device__ int    g_src_sorted[EE];
__device__ double g_acc   [512];
__device__ float  g_scale [256];
__device__ float  g_shift [256];
__device__ int    g_is64;

// ---------------- PTX helpers ---------------------------------------------------
__device__ __forceinline__ uint32_t smem_u32(const void* p) {
    uint32_t a;
    asm("{ .reg .u64 t; cvta.to.shared.u64 t, %1; cvt.u32.u64 %0, t; }" : "=r"(a) : "l"(p));
    return a;
}
#define CP_ASYNC16(sa, g) \
    asm volatile("cp.async.cg.shared.global [%0], [%1], 16;" :: "r"(sa), "l"(g) : "memory")
#define CP_COMMIT() asm volatile("cp.async.commit_group;" ::: "memory")
#define LDSM4(r, a) \
    asm volatile("ldmatrix.sync.aligned.m8n8.x4.shared.b16 {%0,%1,%2,%3}, [%4];" \
        : "=r"((r)[0]), "=r"((r)[1]), "=r"((r)[2]), "=r"((r)[3]) : "r"(a))
#define MMA16816(d, a, b) \
    asm volatile("mma.sync.aligned.m16n8k16.row.col.f32.bf16.bf16.f32 " \
        "{%0,%1,%2,%3}, {%4,%5,%6,%7}, {%8,%9}, {%0,%1,%2,%3};" \
        : "+f"((d)[0]), "+f"((d)[1]), "+f"((d)[2]), "+f"((d)[3]) \
        : "r"((a)[0]), "r"((a)[1]), "r"((a)[2]), "r"((a)[3]), "r"((b)[0]), "r"((b)[1]))

__device__ __forceinline__ float4 ld_hl(const __nv_bfloat16* __restrict__ h,
                                        const __nv_bfloat16* __restrict__ l, size_t off) {
    uint2 uh = *(const uint2*)(h + off);
    uint2 ul = *(const uint2*)(l + off);
    float2 h0 = __bfloat1622float2(*(__nv_bfloat162*)&uh.x);
    float2 h1 = __bfloat1622float2(*(__nv_bfloat162*)&uh.y);
    float2 l0 = __bfloat1622float2(*(__nv_bfloat162*)&ul.x);
    float2 l1 = __bfloat1622float2(*(__nv_bfloat162*)&ul.y);
    return make_float4(h0.x + l0.x, h0.y + l0.y, h1.x + l1.x, h1.y + l1.y);
}

// ---------------- small utility kernels --------------------------------------
__global__ void k_zero_cnt() {
    int i = blockIdx.x * blockDim.x + threadIdx.x;
    if (i < NN) g_cnt[i] = 0;
}
__global__ void k_zero_acc() {
    int i = threadIdx.x;
    if (i < 512) g_acc[i] = 0.0;
}
__global__ void k_detect(const void* edges) {
    const int* p = (const int*)edges;
    int ok = 1;
    for (int i = 0; i < 64; i++)
        if (p[2 * i + 1] != 0) ok = 0;
    g_is64 = ok;
}
__global__ void k_split(const float* __restrict__ in, __nv_bfloat16* __restrict__ h,
                        __nv_bfloat16* __restrict__ l, int n) {
    int i = blockIdx.x * blockDim.x + threadIdx.x;
    if (i < n) {
        float v = in[i];
        __nv_bfloat16 hh = __float2bfloat16_rn(v);
        h[i] = hh;
        l[i] = __float2bfloat16_rn(v - __bfloat162float(hh));
    }
}

// ---------------- CSR construction --------------------------------------------
__global__ void k_hist(const void* edges) {
    int e = blockIdx.x * blockDim.x + threadIdx.x;
    if (e >= EE) return;
    int d;
    if (g_is64) d = (int)((const long long*)edges)[EE + e];
    else        d = ((const int*)edges)[EE + e];
    atomicAdd(&g_cnt[d], 1);
}
__global__ void k_scan1() {
    __shared__ int sh[1024];
    int i = blockIdx.x * 1024 + threadIdx.x;
    int v = (i < NN) ? g_cnt[i] : 0;
    sh[threadIdx.x] = v;
    __syncthreads();
    for (int off = 1; off < 1024; off <<= 1) {
        int t = (threadIdx.x >= off) ? sh[threadIdx.x - off] : 0;
        __syncthreads();
        sh[threadIdx.x] += t;
        __syncthreads();
    }
    if (i < NN) g_offs[i] = sh[threadIdx.x] - v;
    if (threadIdx.x == 1023) g_bsum[blockIdx.x] = sh[1023];
}
__global__ void k_scan2() {
    __shared__ int sh[128];
    int nb = (NN + 1023) / 1024;
    int v = (threadIdx.x < nb) ? g_bsum[threadIdx.x] : 0;
    sh[threadIdx.x] = v;
    __syncthreads();
    for (int off = 1; off < 128; off <<= 1) {
        int t = (threadIdx.x >= off) ? sh[threadIdx.x - off] : 0;
        __syncthreads();
        sh[threadIdx.x] += t;
        __syncthreads();
    }
    g_bsum[threadIdx.x] = sh[threadIdx.x] - v;
}
__global__ void k_scan3() {
    int i = blockIdx.x * blockDim.x + threadIdx.x;
    if (i < NN) {
        int off = g_offs[i] + g_bsum[i >> 10];
        g_offs[i]   = off;
        g_cursor[i] = off;
    }
    if (i == 0) g_offs[NN] = EE;
}
__global__ void k_fill(const void* edges) {
    int e = blockIdx.x * blockDim.x + threadIdx.x;
    if (e >= EE) return;
    int s, d;
    if (g_is64) {
        const long long* p = (const long long*)edges;
        s = (int)p[e]; d = (int)p[EE + e];
    } else {
        const int* p = (const int*)edges;
        s = p[e]; d = p[EE + e];
    }
    int pos = atomicAdd(&g_cursor[d], 1);
    g_src_sorted[pos] = s;
}

// ---------------- aggregation kernels ------------------------------------------
// layer 1: fp32 source -> mean h/l split. D=128: 32 lanes/node, 4 nodes/block.
__global__ void k_agg_f32(const float* __restrict__ x, __nv_bfloat16* __restrict__ mh,
                          __nv_bfloat16* __restrict__ ml) {
    constexpr int G = 32;
    int group = threadIdx.x / G;
    int lane  = threadIdx.x % G;
    int node  = blockIdx.x * 4 + group;
    if (node >= NN) return;
    int beg = g_offs[node], end = g_offs[node + 1];
    float4 a0 = make_float4(0.f, 0.f, 0.f, 0.f);
    float4 a1 = make_float4(0.f, 0.f, 0.f, 0.f);
    const float4* xv = (const float4*)x;
    int e = beg;
    for (; e + 1 < end; e += 2) {
        int s0 = g_src_sorted[e], s1 = g_src_sorted[e + 1];
        float4 v0 = xv[(size_t)s0 * G + lane];
        float4 v1 = xv[(size_t)s1 * G + lane];
        a0.x += v0.x; a0.y += v0.y; a0.z += v0.z; a0.w += v0.w;
        a1.x += v1.x; a1.y += v1.y; a1.z += v1.z; a1.w += v1.w;
    }
    if (e < end) {
        int s0 = g_src_sorted[e];
        float4 v0 = xv[(size_t)s0 * G + lane];
        a0.x += v0.x; a0.y += v0.y; a0.z += v0.z; a0.w += v0.w;
    }
    float inv = 1.0f / fmaxf((float)(end - beg), 1.0f);
    float o[4] = {(a0.x + a1.x) * inv, (a0.y + a1.y) * inv,
                  (a0.z + a1.z) * inv, (a0.w + a1.w) * inv};
    __nv_bfloat16 hv[4], lv[4];
#pragma unroll
    for (int q = 0; q < 4; q++) {
        hv[q] = __float2bfloat16_rn(o[q]);
        lv[q] = __float2bfloat16_rn(o[q] - __bfloat162float(hv[q]));
    }
    size_t base = (size_t)node * 128 + lane * 4;
    *(uint2*)(mh + base) = *(uint2*)hv;
    *(uint2*)(ml + base) = *(uint2*)lv;
}

// layer 2: bf16 h/l source (D=256) -> mean h/l split. 64 lanes/node, 2 nodes/block.
__global__ void k_agg_hl(const __nv_bfloat16* __restrict__ ah, const __nv_bfloat16* __restrict__ al,
                         __nv_bfloat16* __restrict__ mh, __nv_bfloat16* __restrict__ ml) {
    constexpr int G = 64;
    int group = threadIdx.x / G;
    int lane  = threadIdx.x % G;
    int node  = blockIdx.x * 2 + group;
    if (node >= NN) return;
    int beg = g_offs[node], end = g_offs[node + 1];
    float4 a0 = make_float4(0.f, 0.f, 0.f, 0.f);
    float4 a1 = make_float4(0.f, 0.f, 0.f, 0.f);
    int e = beg;
    for (; e + 1 < end; e += 2) {
        int s0 = g_src_sorted[e], s1 = g_src_sorted[e + 1];
        float4 v0 = ld_hl(ah, al, (size_t)s0 * 256 + lane * 4);
        float4 v1 = ld_hl(ah, al, (size_t)s1 * 256 + lane * 4);
        a0.x += v0.x; a0.y += v0.y; a0.z += v0.z; a0.w += v0.w;
        a1.x += v1.x; a1.y += v1.y; a1.z += v1.z; a1.w += v1.w;
    }
    if (e < end) {
        int s0 = g_src_sorted[e];
        float4 v0 = ld_hl(ah, al, (size_t)s0 * 256 + lane * 4);
        a0.x += v0.x; a0.y += v0.y; a0.z += v0.z; a0.w += v0.w;
    }
    float inv = 1.0f / fmaxf((float)(end - beg), 1.0f);
    float o[4] = {(a0.x + a1.x) * inv, (a0.y + a1.y) * inv,
                  (a0.z + a1.z) * inv, (a0.w + a1.w) * inv};
    __nv_bfloat16 hv[4], lv[4];
#pragma unroll
    for (int q = 0; q < 4; q++) {
        hv[q] = __float2bfloat16_rn(o[q]);
        lv[q] = __float2bfloat16_rn(o[q] - __bfloat162float(hv[q]));
    }
    size_t base = (size_t)node * 256 + lane * 4;
    *(uint2*)(mh + base) = *(uint2*)hv;
    *(uint2*)(ml + base) = *(uint2*)lv;
}

// layer 3 post-aggregation: Z [N,256] = [ZL|ZR]; pre3[i] = mean_j ZL[j] + ZR[i].
__global__ void k_agg_post(const float* __restrict__ Z, float* __restrict__ pre3) {
    constexpr int G = 32;
    int group = threadIdx.x / G;
    int lane  = threadIdx.x % G;
    int node  = blockIdx.x * 4 + group;
    if (node >= NN) return;
    int beg = g_offs[node], end = g_offs[node + 1];
    float4 a0 = make_float4(0.f, 0.f, 0.f, 0.f);
    float4 a1 = make_float4(0.f, 0.f, 0.f, 0.f);
    int e = beg;
    for (; e + 1 < end; e += 2) {
        int s0 = g_src_sorted[e], s1 = g_src_sorted[e + 1];
        float4 v0 = *(const float4*)(Z + (size_t)s0 * 256 + lane * 4);
        float4 v1 = *(const float4*)(Z + (size_t)s1 * 256 + lane * 4);
        a0.x += v0.x; a0.y += v0.y; a0.z += v0.z; a0.w += v0.w;
        a1.x += v1.x; a1.y += v1.y; a1.z += v1.z; a1.w += v1.w;
    }
    if (e < end) {
        int s0 = g_src_sorted[e];
        float4 v0 = *(const float4*)(Z + (size_t)s0 * 256 + lane * 4);
        a0.x += v0.x; a0.y += v0.y; a0.z += v0.z; a0.w += v0.w;
    }
    float inv = 1.0f / fmaxf((float)(end - beg), 1.0f);
    float4 r = *(const float4*)(Z + (size_t)node * 256 + 128 + lane * 4);
    float4 o;
    o.x = (a0.x + a1.x) * inv + r.x;
    o.y = (a0.y + a1.y) * inv + r.y;
    o.z = (a0.z + a1.z) * inv + r.z;
    o.w = (a0.w + a1.w) * inv + r.w;
    *(float4*)(pre3 + (size_t)node * 128 + lane * 4) = o;
}

// ---------------- mma.sync dual GEMM + hi/lo compensation + fused stats --------
template <int DI, int DO, int NSEG, bool STATS>
__global__ __launch_bounds__(256) void k_gemm_mma(
    const __nv_bfloat16* __restrict__ A1h, const __nv_bfloat16* __restrict__ A1l,
    const __nv_bfloat16* __restrict__ A2h, const __nv_bfloat16* __restrict__ A2l,
    const __nv_bfloat16* __restrict__ B1h, const __nv_bfloat16* __restrict__ B1l,
    const __nv_bfloat16* __restrict__ B2h, const __nv_bfloat16* __restrict__ B2l,
    float* __restrict__ C)
{
    constexpr int CH_PER_SEG = DI / 32;
    constexpr int NCH = NSEG * CH_PER_SEG;
    __shared__ __align__(128) char smem[2 * 2 * 128 * 80];
    __shared__ float cs[128], cq[128];
    const uint32_t sbase = smem_u32(smem);
    const int tid = threadIdx.x;
    const int wid = tid >> 5, lane = tid & 31;
    const int wr = wid >> 2, wcn = wid & 3;
    const int rowBase = blockIdx.x * 128;
    const int colBase = blockIdx.y * 128;

    const __nv_bfloat16* Asrc[6] = {A1h, A1h, A1l, A2h, A2h, A2l};
    const __nv_bfloat16* Bsrc[6] = {B1h, B1l, B1h, B2h, B2l, B2h};

    const int lrow = tid >> 2;
    const int lcg  = tid & 3;
    const uint32_t sA0 = sbase + lrow * 80 + lcg * 16;
    const uint32_t sB0 = sbase + 10240 + lrow * 80 + lcg * 16;

    auto load = [&](int c) {
        const int s = c & 1;
        const int seg = c / CH_PER_SEG;
        const int kk = (c % CH_PER_SEG) * 32;
        const __nv_bfloat16* Ap = Asrc[seg] + (size_t)rowBase * DI + kk + lcg * 8;
        const __nv_bfloat16* Bp = Bsrc[seg] + (size_t)colBase * DI + kk + lcg * 8;
        const uint32_t so = s * 20480u;
        CP_ASYNC16(sA0 + so,        Ap + (size_t)lrow * DI);
        CP_ASYNC16(sA0 + so + 5120, Ap + (size_t)(lrow + 64) * DI);
        CP_ASYNC16(sB0 + so,        Bp + (size_t)lrow * DI);
        CP_ASYNC16(sB0 + so + 5120, Bp + (size_t)(lrow + 64) * DI);
        CP_COMMIT();
    };

    float acc[4][4][4] = {};
    const uint32_t aAddr = sbase + (wr * 64 + (lane & 15)) * 80 + (lane >> 4) * 16;
    const uint32_t bAddr = sbase + 10240 +
        (wcn * 32 + (lane & 7) + ((lane >> 4) << 3)) * 80 + ((lane >> 3) & 1) * 16;

    load(0);
    for (int c = 0; c < NCH; c++) {
        const int s = c & 1;
        if (c + 1 < NCH) {
            load(c + 1);
            asm volatile("cp.async.wait_group 1;" ::: "memory");
        } else {
            asm volatile("cp.async.wait_group 0;" ::: "memory");
        }
        __syncthreads();
        const uint32_t so = s * 20480u;
#pragma unroll
        for (int kb = 0; kb < 2; kb++) {
            uint32_t afr[4][4], bfr[4][2];
#pragma unroll
            for (int mt = 0; mt < 4; mt++)
                LDSM4(afr[mt], aAddr + so + mt * (16 * 80) + kb * 32);
#pragma unroll
            for (int ntp = 0; ntp < 2; ntp++) {
                uint32_t r[4];
                LDSM4(r, bAddr + so + ntp * (16 * 80) + kb * 32);
                bfr[ntp * 2][0] = r[0]; bfr[ntp * 2][1] = r[1];
                bfr[ntp * 2 + 1][0] = r[2]; bfr[ntp * 2 + 1][1] = r[3];
            }
#pragma unroll
            for (int mt = 0; mt < 4; mt++)
#pragma unroll
                for (int nt = 0; nt < 4; nt++)
                    MMA16816(acc[mt][nt], afr[mt], bfr[nt]);
        }
        __syncthreads();
    }

    // write C
#pragma unroll
    for (int mt = 0; mt < 4; mt++) {
        const int r0 = rowBase + wr * 64 + mt * 16 + (lane >> 2);
#pragma unroll
        for (int nt = 0; nt < 4; nt++) {
            const int cc = colBase + wcn * 32 + nt * 8 + (lane & 3) * 2;
            if (r0 < NN)
                *(float2*)(C + (size_t)r0 * DO + cc) =
                    make_float2(acc[mt][nt][0], acc[mt][nt][1]);
            if (r0 + 8 < NN)
                *(float2*)(C + (size_t)(r0 + 8) * DO + cc) =
                    make_float2(acc[mt][nt][2], acc[mt][nt][3]);
        }
    }

    if (STATS) {
        // pad rows (>= NN) have zero A operands -> zero acc -> contribute nothing
        if (tid < 128) { cs[tid] = 0.f; cq[tid] = 0.f; }
        __syncthreads();
#pragma unroll
        for (int nt = 0; nt < 4; nt++) {
            float s0 = 0.f, q0 = 0.f, s1 = 0.f, q1 = 0.f;
#pragma unroll
            for (int mt = 0; mt < 4; mt++) {
                float a0 = acc[mt][nt][0], a1 = acc[mt][nt][1];
                float a2 = acc[mt][nt][2], a3 = acc[mt][nt][3];
                s0 += a0 + a2; q0 += a0 * a0 + a2 * a2;
                s1 += a1 + a3; q1 += a1 * a1 + a3 * a3;
            }
            int cc = wcn * 32 + nt * 8 + (lane & 3) * 2;
            atomicAdd(&cs[cc], s0);     atomicAdd(&cq[cc], q0);
            atomicAdd(&cs[cc + 1], s1); atomicAdd(&cq[cc + 1], q1);
        }
        __syncthreads();
        if (tid < 128) {
            atomicAdd(&g_acc[colBase + tid],       (double)cs[tid]);
            atomicAdd(&g_acc[256 + colBase + tid], (double)cq[tid]);
        }
    }
}

// ---------------- BN finalize / apply -------------------------------------------
template <int D>
__global__ void k_stats(const float* __restrict__ pre) {
    constexpr int RPI = 256 / D;
    int col = threadIdx.x % D;
    int rl  = threadIdx.x / D;
    double s = 0.0, sq = 0.0;
    for (int r = blockIdx.x * RPI + rl; r < NN; r += gridDim.x * RPI) {
        float v = pre[(size_t)r * D + col];
        s  += (double)v;
        sq += (double)v * (double)v;
    }
    if (RPI == 2) {
        __shared__ double sh1[256], sh2[256];
        sh1[threadIdx.x] = s; sh2[threadIdx.x] = sq;
        __syncthreads();
        if (rl == 0) { s += sh1[threadIdx.x + D]; sq += sh2[threadIdx.x + D]; }
    }
    if (rl == 0) {
        atomicAdd(&g_acc[col], s);
        atomicAdd(&g_acc[256 + col], sq);
    }
}
template <int D>
__global__ void k_finalize(const float* __restrict__ g, const float* __restrict__ b) {
    int c = threadIdx.x;
    if (c < D) {
        double mu  = g_acc[c] / (double)NN;
        double var = g_acc[256 + c] / (double)NN - mu * mu;
        double rs  = 1.0 / sqrt(var + BN_EPS);
        double sc  = (double)g[c] * rs;
        g_scale[c] = (float)sc;
        g_shift[c] = (float)((double)b[c] - mu * sc);
    }
}
// BN + ReLU -> bf16 hi/lo only (no fp32 activation array)
template <int D>
__global__ void k_bn_hl(const float* __restrict__ in,
                        __nv_bfloat16* __restrict__ outH, __nv_bfloat16* __restrict__ outL) {
    int i = blockIdx.x * blockDim.x + threadIdx.x;
    int total4 = NN * D / 4;
    if (i >= total4) return;
    int c4 = (i & (D / 4 - 1)) * 4;
    float4 v  = ((const float4*)in)[i];
    float4 sc = *(const float4*)&g_scale[c4];
    float4 sh = *(const float4*)&g_shift[c4];
    float o[4];
    o[0] = fmaxf(v.x * sc.x + sh.x, 0.f);
    o[1] = fmaxf(v.y * sc.y + sh.y, 0.f);
    o[2] = fmaxf(v.z * sc.z + sh.z, 0.f);
    o[3] = fmaxf(v.w * sc.w + sh.w, 0.f);
    __nv_bfloat16 hv[4], lv[4];
#pragma unroll
    for (int q = 0; q < 4; q++) {
        hv[q] = __float2bfloat16_rn(o[q]);
        lv[q] = __float2bfloat16_rn(o[q] - __bfloat162float(hv[q]));
    }
    *(uint2*)(outH + (size_t)i * 4) = *(uint2*)hv;
    *(uint2*)(outL + (size_t)i * 4) = *(uint2*)lv;
}

// fused BN + ReLU + classifier (layer 3): pre3 [N,128] -> out [N,15]
__global__ __launch_bounds__(256) void k_bn_cls(
    const float* __restrict__ pre3, const float* __restrict__ wc,
    const float* __restrict__ bc, float* __restrict__ out)
{
    __shared__ float4 wsh[NCLS * 32];
    __shared__ float  bsh[NCLS];
    int tid = threadIdx.x;
    for (int i = tid; i < NCLS * 32; i += 256) wsh[i] = ((const float4*)wc)[i];
    if (tid < NCLS) bsh[tid] = bc[tid];
    __syncthreads();
    int warp = tid >> 5, lane = tid & 31;
    int row = blockIdx.x * 8 + warp;
    if (row >= NN) return;
    float4 v  = ((const float4*)pre3)[(size_t)row * 32 + lane];
    float4 sc = *(const float4*)&g_scale[lane * 4];
    float4 sh = *(const float4*)&g_shift[lane * 4];
    float4 hv;
    hv.x = fmaxf(v.x * sc.x + sh.x, 0.f);
    hv.y = fmaxf(v.y * sc.y + sh.y, 0.f);
    hv.z = fmaxf(v.z * sc.z + sh.z, 0.f);
    hv.w = fmaxf(v.w * sc.w + sh.w, 0.f);
#pragma unroll
    for (int j = 0; j < NCLS; j++) {
        float4 w = wsh[j * 32 + lane];
        float p = hv.x * w.x + hv.y * w.y + hv.z * w.z + hv.w * w.w;
#pragma unroll
        for (int o = 16; o > 0; o >>= 1) p += __shfl_xor_sync(0xFFFFFFFFu, p, o);
        if (lane == 0) out[(size_t)row * NCLS + j] = p + bsh[j];
    }
}

// ---------------- driver --------------------------------------------------------
extern "C" void kernel_launch(void* const* d_in, const int* in_sizes, int n_in,
                              void* d_out, int out_size)
{
    const float* x     = (const float*)d_in[0];
    const void*  edges = d_in[1];
    const float* w1_l = (const float*)d_in[2];
    const float* w1_r = (const float*)d_in[4];
    const float* g1   = (const float*)d_in[5];
    const float* be1  = (const float*)d_in[6];
    const float* w2_l = (const float*)d_in[7];
    const float* w2_r = (const float*)d_in[9];
    const float* g2   = (const float*)d_in[10];
    const float* be2  = (const float*)d_in[11];
    const float* w3_l = (const float*)d_in[12];
    const float* w3_r = (const float*)d_in[14];
    const float* g3   = (const float*)d_in[15];
    const float* be3  = (const float*)d_in[16];
    const float* wc   = (const float*)d_in[17];
    const float* bc   = (const float*)d_in[18];
    float* out = (float*)d_out;

    static float *pre = nullptr, *pre3 = nullptr;
    static __nv_bfloat16 *meanH, *meanL, *actH, *actL, *xH, *xL, *wbuf;
    if (!pre) {
        cudaGetSymbolAddress((void**)&pre,   g_pre);
        cudaGetSymbolAddress((void**)&pre3,  g_pre3);
        cudaGetSymbolAddress((void**)&meanH, g_meanH);
        cudaGetSymbolAddress((void**)&meanL, g_meanL);
        cudaGetSymbolAddress((void**)&actH,  g_actH);
        cudaGetSymbolAddress((void**)&actL,  g_actL);
        cudaGetSymbolAddress((void**)&xH,    g_xH);
        cudaGetSymbolAddress((void**)&xL,    g_xL);
        cudaGetSymbolAddress((void**)&wbuf,  g_w);
    }
    auto W = [&](int i) { return wbuf + (size_t)i * 65536; };

    const int EB = (EE + 255) / 256;
    const int NB = (NN + 255) / 256;

    // ---- CSR build ----
    k_detect<<<1, 1>>>(edges);
    k_zero_cnt<<<NB, 256>>>();
    k_hist<<<EB, 256>>>(edges);
    k_scan1<<<(NN + 1023) / 1024, 1024>>>();
    k_scan2<<<1, 128>>>();
    k_scan3<<<NB, 256>>>();
    k_fill<<<EB, 256>>>(edges);

    // ---- splits: weights + x ----
    k_split<<<(32768 + 255) / 256, 256>>>(w1_l, W(0), W(1), 256 * 128);
    k_split<<<(32768 + 255) / 256, 256>>>(w1_r, W(2), W(3), 256 * 128);
    k_split<<<(65536 + 255) / 256, 256>>>(w2_l, W(4), W(5), 256 * 256);
    k_split<<<(65536 + 255) / 256, 256>>>(w2_r, W(6), W(7), 256 * 256);
    // layer-3 combined B: rows [w3_l ; w3_r]
    k_split<<<(32768 + 255) / 256, 256>>>(w3_l, W(8), W(9), 128 * 256);
    k_split<<<(32768 + 255) / 256, 256>>>(w3_r, W(8) + 32768, W(9) + 32768, 128 * 256);
    k_split<<<(NN * 128 + 255) / 256, 256>>>(x, xH, xL, NN * 128);

    const int MT = NN_PAD / 128;  // 782 M-tiles

    // ---- layer 1: 128 -> 256 (dual GEMM, stats fused) ----
    k_agg_f32<<<(NN + 3) / 4, 128>>>(x, meanH, meanL);
    k_zero_acc<<<1, 512>>>();
    k_gemm_mma<128, 256, 6, true><<<dim3(MT, 2), 256>>>(meanH, meanL, xH, xL,
                                                        W(0), W(1), W(2), W(3), pre);
    k_finalize<C1><<<1, 256>>>(g1, be1);
    k_bn_hl<C1><<<(NN * C1 / 4 + 255) / 256, 256>>>(pre, actH, actL);

    // ---- layer 2: 256 -> 256 (dual GEMM, stats fused) ----
    k_agg_hl<<<(NN + 1) / 2, 128>>>(actH, actL, meanH, meanL);
    k_zero_acc<<<1, 512>>>();
    k_gemm_mma<256, 256, 6, true><<<dim3(MT, 2), 256>>>(meanH, meanL, actH, actL,
                                                        W(4), W(5), W(6), W(7), pre);
    k_finalize<C1><<<1, 256>>>(g2, be2);
    k_bn_hl<C1><<<(NN * C1 / 4 + 255) / 256, 256>>>(pre, actH, actL);

    // ---- layer 3: 256 -> 128, post-aggregation ----
    // Z = [h @ w3_l^T | h @ w3_r^T]  (single-A GEMM, 3 K-segments, DO=256)
    k_gemm_mma<256, 256, 3, false><<<dim3(MT, 2), 256>>>(actH, actL, nullptr, nullptr,
                                                         W(8), W(9), nullptr, nullptr, pre);
    k_agg_post<<<(NN + 3) / 4, 128>>>(pre, pre3);
    k_zero_acc<<<1, 512>>>();
    k_stats<C3><<<1024, 256>>>(pre3);
    k_finalize<C3><<<1, 128>>>(g3, be3);

    // ---- fused BN + ReLU + classifier ----
    k_bn_cls<<<(NN + 7) / 8, 256>>>(pre3, wc, bc, out);
}